// round 8
// baseline (speedup 1.0000x reference)
#include <cuda_runtime.h>
#include <cstdint>

#define KDIM 7168
#define ODIM 16384
#define MDIM 32
#define OTILE 64
#define KTILE 128
#define NKT (KDIM / KTILE)     /* 56 */
#define NTHREADS 256           /* 8 warps = 4 ks-quarters x 2 row-warps */
#define STRIDE 132             /* 128 + 4 pad floats -> conflict-free fragment LDS */
#define W_STAGE_F (OTILE * STRIDE)   /* 8448 floats */
#define X_STAGE_F (MDIM * STRIDE)    /* 4224 floats */
#define NSTAGE 2

// smem: [W0][W1][X0][X1] = 2*8448 + 2*4224 floats = 101,376 B -> 2 CTAs/SM
#define SMEM_FLOATS (NSTAGE * (W_STAGE_F + X_STAGE_F))

// pre-rounded tf32 x (0.92 MB scratch; device globals are allowed)
__device__ uint32_t g_xtf[MDIM * KDIM];

__device__ __forceinline__ uint32_t smem_u32(const void* p) {
    uint32_t a;
    asm("{ .reg .u64 t; cvta.to.shared.u64 t, %1; cvt.u32.u64 %0, t; }" : "=r"(a) : "l"(p));
    return a;
}

__device__ __forceinline__ uint32_t tf32r(float v) {   // fp32 -> tf32 round-to-nearest
    uint32_t u;
    asm("cvt.rna.tf32.f32 %0, %1;" : "=r"(u) : "f"(v));
    return u;
}

__device__ __forceinline__ void cp_async16(uint32_t dst_smem, const void* src) {
    asm volatile("cp.async.cg.shared.global [%0], [%1], 16;" :: "r"(dst_smem), "l"(src) : "memory");
}
#define CP_COMMIT() asm volatile("cp.async.commit_group;" ::: "memory")
#define CP_WAIT0()  asm volatile("cp.async.wait_group 0;" ::: "memory")

#define MMA_TF32(acc, a0, a1, a2, a3, b0, b1)                                  \
    asm volatile(                                                              \
        "mma.sync.aligned.m16n8k8.row.col.f32.tf32.tf32.f32 "                  \
        "{%0,%1,%2,%3}, {%4,%5,%6,%7}, {%8,%9}, {%0,%1,%2,%3};"                \
        : "+f"((acc)[0]), "+f"((acc)[1]), "+f"((acc)[2]), "+f"((acc)[3])       \
        : "r"(a0), "r"(a1), "r"(a2), "r"(a3), "r"(b0), "r"(b1))

// ---- prologue kernel: round x to tf32 once ----
__global__ void round_x_kernel(const float* __restrict__ X) {
    int i = blockIdx.x * blockDim.x + threadIdx.x;
    if (i < MDIM * KDIM) g_xtf[i] = tf32r(X[i]);
}

__global__ __launch_bounds__(NTHREADS, 2)
void linear_tf32_mma(const float* __restrict__ W,
                     const float* __restrict__ S, float* __restrict__ out)
{
    extern __shared__ float smem[];
    float*    wbuf = smem;                                   // 2 W stages
    uint32_t* xbuf = reinterpret_cast<uint32_t*>(smem + NSTAGE * W_STAGE_F);

    const int tid  = threadIdx.x;
    const int lane = tid & 31;
    const int w    = tid >> 5;          // 0..7
    const int q    = w >> 1;            // ks-quarter (0..3)
    const int wrow = w & 1;             // row-warp: o rows [wrow*32, wrow*32+32)
    const int bx   = blockIdx.x;
    const int o_base = bx * OTILE;
    const int srow = bx >> 1;           // scale blocks are 128 o-rows

    const int g = lane >> 2;   // 0..7
    const int c = lane & 3;    // 0..3

    float acc[2][4][4];
    #pragma unroll
    for (int b = 0; b < 2; b++)
        #pragma unroll
        for (int i = 0; i < 4; i++)
            #pragma unroll
            for (int j = 0; j < 4; j++) acc[b][i][j] = 0.0f;

    // cp.async coordinates (chunk = 16B):
    const int wr0 = tid >> 5;   // W: rows wr0 + 8*i (i<8), chunk col = lane
    const int xm0 = tid >> 5;   // X: rows xm0 (i=0) / xm0+8..+24, but 1024 chunks/256thr = 4 each
    const uint32_t wsm = smem_u32(wbuf);
    const uint32_t xsm = smem_u32(xbuf);

    const uint32_t* xtf = g_xtf;

    // ---- issue helper (inlined twice): load tile kt into slot st ----
    #define ISSUE_TILE(kt_, st_) do {                                                    \
        const uint32_t wd = wsm + (uint32_t)(st_) * (W_STAGE_F * 4);                     \
        const uint32_t xd = xsm + (uint32_t)(st_) * (X_STAGE_F * 4);                     \
        const float* gw = W + (size_t)o_base * KDIM + (size_t)(kt_) * KTILE;             \
        const uint32_t* gx = xtf + (size_t)(kt_) * KTILE;                                \
        _Pragma("unroll")                                                                \
        for (int i_ = 0; i_ < 8; i_++) {                                                 \
            int row_ = wr0 + i_ * 8;                                                     \
            cp_async16(wd + (uint32_t)(row_ * STRIDE + lane * 4) * 4u,                   \
                       gw + (size_t)row_ * KDIM + (size_t)lane * 4);                     \
        }                                                                                \
        _Pragma("unroll")                                                                \
        for (int i_ = 0; i_ < 4; i_++) {                                                 \
            int m_ = xm0 + i_ * 8;                                                       \
            cp_async16(xd + (uint32_t)(m_ * STRIDE + lane * 4) * 4u,                     \
                       gx + (size_t)m_ * KDIM + (size_t)lane * 4);                       \
        }                                                                                \
    } while (0)

    // prologue: tile 0
    ISSUE_TILE(0, 0);
    CP_COMMIT();

    float s_cur = S[(size_t)srow * NKT];   // scale for kt=0 (L2 hit, overlaps cp.async)

    #pragma unroll 1
    for (int kt = 0; kt < NKT; kt++) {
        CP_WAIT0();            // tile kt complete (own groups)
        __syncthreads();       // publish cp.async fills; all warps done reading kt-1's slot

        // issue tile kt+1 into the slot freed at iteration kt-1
        if (kt + 1 < NKT) {
            ISSUE_TILE(kt + 1, (kt + 1) & 1);
        }
        CP_COMMIT();

        const float s = s_cur;
        if (kt + 1 < NKT) s_cur = S[(size_t)srow * NKT + kt + 1];   // prefetch next scale

        const float*    wstage = wbuf + (kt & 1) * W_STAGE_F;
        const uint32_t* xstage = xbuf + (kt & 1) * X_STAGE_F;
        const int r0 = wrow * 32 + g;

        #pragma unroll
        for (int ks = 0; ks < 4; ks++) {
            const int k0 = q * 32 + ks * 8;

            uint32_t a[2][4];
            #pragma unroll
            for (int b = 0; b < 2; b++) {
                const int r = r0 + b * 16;
                a[b][0] = tf32r(s * wstage[ r      * STRIDE + k0 + c    ]);
                a[b][1] = tf32r(s * wstage[(r + 8) * STRIDE + k0 + c    ]);
                a[b][2] = tf32r(s * wstage[ r      * STRIDE + k0 + c + 4]);
                a[b][3] = tf32r(s * wstage[(r + 8) * STRIDE + k0 + c + 4]);
            }

            #pragma unroll
            for (int mt = 0; mt < 4; mt++) {
                uint32_t b0 = xstage[(mt * 8 + g) * STRIDE + k0 + c];
                uint32_t b1 = xstage[(mt * 8 + g) * STRIDE + k0 + 4 + c];
                MMA_TF32(acc[0][mt], a[0][0], a[0][1], a[0][2], a[0][3], b0, b1);
                MMA_TF32(acc[1][mt], a[1][0], a[1][1], a[1][2], a[1][3], b0, b1);
            }
        }
        // no trailing barrier: next iteration's top barrier protects slot reuse
    }

    // ---- epilogue: reduce the 4 ks-quarters, then store ----
    __syncthreads();                     // all MMA reads of wbuf done
    float4* red = reinterpret_cast<float4*>(wbuf);   // 24,576 B scratch
    if (q > 0) {
        #pragma unroll
        for (int b = 0; b < 2; b++)
            #pragma unroll
            for (int mt = 0; mt < 4; mt++)
                red[(((q - 1) * 2 + wrow) * 8 + b * 4 + mt) * 32 + lane] =
                    make_float4(acc[b][mt][0], acc[b][mt][1], acc[b][mt][2], acc[b][mt][3]);
    }
    __syncthreads();

    if (q == 0) {
        #pragma unroll
        for (int b = 0; b < 2; b++) {
            const int o0 = o_base + wrow * 32 + b * 16 + g;
            #pragma unroll
            for (int mt = 0; mt < 4; mt++) {
                float4 r = make_float4(acc[b][mt][0], acc[b][mt][1],
                                       acc[b][mt][2], acc[b][mt][3]);
                #pragma unroll
                for (int qq = 0; qq < 3; qq++) {
                    float4 v = red[((qq * 2 + wrow) * 8 + b * 4 + mt) * 32 + lane];
                    r.x += v.x; r.y += v.y; r.z += v.z; r.w += v.w;
                }
                const int m0 = mt * 8 + c * 2;
                out[(size_t)m0       * ODIM + o0    ] = r.x;
                out[(size_t)(m0 + 1) * ODIM + o0    ] = r.y;
                out[(size_t)m0       * ODIM + o0 + 8] = r.z;
                out[(size_t)(m0 + 1) * ODIM + o0 + 8] = r.w;
            }
        }
    }
}

extern "C" void kernel_launch(void* const* d_in, const int* in_sizes, int n_in,
                              void* d_out, int out_size) {
    const float* x = (const float*)d_in[0];
    const float* w = (const float*)d_in[1];
    const float* s = (const float*)d_in[2];
    float* out = (float*)d_out;

    round_x_kernel<<<(MDIM * KDIM + 255) / 256, 256>>>(x);

    const size_t smem_bytes = SMEM_FLOATS * sizeof(float);
    cudaFuncSetAttribute(linear_tf32_mma,
                         cudaFuncAttributeMaxDynamicSharedMemorySize, (int)smem_bytes);
    linear_tf32_mma<<<ODIM / OTILE, NTHREADS, smem_bytes>>>(w, s, out);
}

// round 9
// speedup vs baseline: 1.0557x; 1.0557x over previous
#include <cuda_runtime.h>
#include <cstdint>

#define KDIM 7168
#define ODIM 16384
#define MDIM 32
#define OTILE 64
#define KTILE 64
#define NKT (KDIM / KTILE)     /* 112 */
#define NSC  56                /* scale cols (128-wide k blocks) */
#define NTHREADS 256           /* 8 warps = 4 ks-quarters x 2 row-warps */
#define STRIDE 68              /* 64 + 4 pad floats; 68 mod 32 = 4 -> bank 4g+c, conflict-free */
#define W_STAGE_F (OTILE * STRIDE)   /* 4352 floats = 17,408 B */
#define X_STAGE_F (MDIM * STRIDE)    /* 2176 floats =  8,704 B */
#define NSTAGE 4

// smem: 4 * (17408 + 8704) = 104,448 B per CTA -> 2 CTAs/SM
#define SMEM_FLOATS (NSTAGE * (W_STAGE_F + X_STAGE_F))

// pre-rounded tf32 x (0.92 MB device scratch; allowed)
__device__ uint32_t g_xtf[MDIM * KDIM];

__device__ __forceinline__ uint32_t smem_u32(const void* p) {
    uint32_t a;
    asm("{ .reg .u64 t; cvta.to.shared.u64 t, %1; cvt.u32.u64 %0, t; }" : "=r"(a) : "l"(p));
    return a;
}

__device__ __forceinline__ uint32_t tf32r(float v) {   // fp32 -> tf32 round-to-nearest
    uint32_t u;
    asm("cvt.rna.tf32.f32 %0, %1;" : "=r"(u) : "f"(v));
    return u;
}

__device__ __forceinline__ void cp_async16(uint32_t dst_smem, const void* src) {
    asm volatile("cp.async.cg.shared.global [%0], [%1], 16;" :: "r"(dst_smem), "l"(src) : "memory");
}
#define CP_COMMIT() asm volatile("cp.async.commit_group;" ::: "memory")
#define CP_WAIT2()  asm volatile("cp.async.wait_group 2;" ::: "memory")

#define MMA_TF32(acc, a0, a1, a2, a3, b0, b1)                                  \
    asm volatile(                                                              \
        "mma.sync.aligned.m16n8k8.row.col.f32.tf32.tf32.f32 "                  \
        "{%0,%1,%2,%3}, {%4,%5,%6,%7}, {%8,%9}, {%0,%1,%2,%3};"                \
        : "+f"((acc)[0]), "+f"((acc)[1]), "+f"((acc)[2]), "+f"((acc)[3])       \
        : "r"(a0), "r"(a1), "r"(a2), "r"(a3), "r"(b0), "r"(b1))

// ---- prologue kernel: round x to tf32 once ----
__global__ void round_x_kernel(const float* __restrict__ X) {
    int i = blockIdx.x * blockDim.x + threadIdx.x;
    if (i < MDIM * KDIM) g_xtf[i] = tf32r(X[i]);
}

__global__ __launch_bounds__(NTHREADS, 2)
void linear_tf32_mma(const float* __restrict__ W,
                     const float* __restrict__ S, float* __restrict__ out)
{
    extern __shared__ float smem[];
    float*    wbuf = smem;                                       // 4 W stages
    uint32_t* xbuf = reinterpret_cast<uint32_t*>(smem + NSTAGE * W_STAGE_F);

    const int tid  = threadIdx.x;
    const int lane = tid & 31;
    const int w    = tid >> 5;          // 0..7
    const int q    = w >> 1;            // ks-quarter (0..3): owns ks {2q, 2q+1} of 8
    const int wrow = w & 1;             // row-warp: o rows [wrow*32, wrow*32+32)
    const int bx   = blockIdx.x;
    const int o_base = bx * OTILE;
    const int srow = bx >> 1;           // scale blocks are 128 o-rows

    const int g = lane >> 2;   // 0..7
    const int c = lane & 3;    // 0..3

    float acc[2][4][4];
    #pragma unroll
    for (int b = 0; b < 2; b++)
        #pragma unroll
        for (int i = 0; i < 4; i++)
            #pragma unroll
            for (int j = 0; j < 4; j++) acc[b][i][j] = 0.0f;

    const uint32_t wsm = smem_u32(wbuf);
    const uint32_t xsm = smem_u32(xbuf);
    const uint32_t* xtf = g_xtf;

    // ---- tile loader: W tile 64x64 (1024 chunks, 4/thread), X tile 32x64 (512, 2/thread)
    #define ISSUE_TILE(kt_, st_) do {                                                    \
        const uint32_t wd = wsm + (uint32_t)(st_) * (W_STAGE_F * 4);                     \
        const uint32_t xd = xsm + (uint32_t)(st_) * (X_STAGE_F * 4);                     \
        const float* gw = W + (size_t)o_base * KDIM + (size_t)(kt_) * KTILE;             \
        const uint32_t* gx = xtf + (size_t)(kt_) * KTILE;                                \
        _Pragma("unroll")                                                                \
        for (int i_ = 0; i_ < 4; i_++) {                                                 \
            int idx_ = i_ * NTHREADS + tid;                                              \
            int row_ = idx_ >> 4, col_ = idx_ & 15;                                      \
            cp_async16(wd + (uint32_t)(row_ * STRIDE + col_ * 4) * 4u,                   \
                       gw + (size_t)row_ * KDIM + (size_t)col_ * 4);                     \
        }                                                                                \
        _Pragma("unroll")                                                                \
        for (int i_ = 0; i_ < 2; i_++) {                                                 \
            int idx_ = i_ * NTHREADS + tid;                                              \
            int row_ = idx_ >> 4, col_ = idx_ & 15;                                      \
            cp_async16(xd + (uint32_t)(row_ * STRIDE + col_ * 4) * 4u,                   \
                       gx + (size_t)row_ * KDIM + (size_t)col_ * 4);                     \
        }                                                                                \
    } while (0)

    // prologue: tiles 0,1,2 in flight
    ISSUE_TILE(0, 0); CP_COMMIT();
    ISSUE_TILE(1, 1); CP_COMMIT();
    ISSUE_TILE(2, 2); CP_COMMIT();

    #pragma unroll 1
    for (int kt = 0; kt < NKT; kt++) {
        CP_WAIT2();            // tile kt complete (<=2 groups pending: kt+1, kt+2)
        __syncthreads();       // publish fills; all warps done reading slot (kt+3)&3 = (kt-1)&3

        // keep depth: issue tile kt+3 into the slot freed at iteration kt-1
        if (kt + 3 < NKT) {
            ISSUE_TILE(kt + 3, (kt + 3) & 3);
        }
        CP_COMMIT();

        const float s = S[(size_t)srow * NSC + (kt >> 1)];

        const float*    wstage = wbuf + (kt & 3) * W_STAGE_F;
        const uint32_t* xstage = xbuf + (kt & 3) * X_STAGE_F;
        const int r0 = wrow * 32 + g;

        #pragma unroll
        for (int ks = 0; ks < 2; ks++) {
            const int k0 = q * 16 + ks * 8;

            uint32_t a[2][4];
            #pragma unroll
            for (int b = 0; b < 2; b++) {
                const int r = r0 + b * 16;
                a[b][0] = tf32r(s * wstage[ r      * STRIDE + k0 + c    ]);
                a[b][1] = tf32r(s * wstage[(r + 8) * STRIDE + k0 + c    ]);
                a[b][2] = tf32r(s * wstage[ r      * STRIDE + k0 + c + 4]);
                a[b][3] = tf32r(s * wstage[(r + 8) * STRIDE + k0 + c + 4]);
            }

            #pragma unroll
            for (int mt = 0; mt < 4; mt++) {
                uint32_t b0 = xstage[(mt * 8 + g) * STRIDE + k0 + c];
                uint32_t b1 = xstage[(mt * 8 + g) * STRIDE + k0 + 4 + c];
                MMA_TF32(acc[0][mt], a[0][0], a[0][1], a[0][2], a[0][3], b0, b1);
                MMA_TF32(acc[1][mt], a[1][0], a[1][1], a[1][2], a[1][3], b0, b1);
            }
        }
        // no trailing barrier: the next iteration's top barrier protects slot reuse
    }

    // ---- epilogue: reduce the 4 ks-quarters, then store ----
    __syncthreads();
    float4* red = reinterpret_cast<float4*>(wbuf);   // 24,576 B scratch in retired wbuf
    if (q > 0) {
        #pragma unroll
        for (int b = 0; b < 2; b++)
            #pragma unroll
            for (int mt = 0; mt < 4; mt++)
                red[(((q - 1) * 2 + wrow) * 8 + b * 4 + mt) * 32 + lane] =
                    make_float4(acc[b][mt][0], acc[b][mt][1], acc[b][mt][2], acc[b][mt][3]);
    }
    __syncthreads();

    if (q == 0) {
        #pragma unroll
        for (int b = 0; b < 2; b++) {
            const int o0 = o_base + wrow * 32 + b * 16 + g;
            #pragma unroll
            for (int mt = 0; mt < 4; mt++) {
                float4 r = make_float4(acc[b][mt][0], acc[b][mt][1],
                                       acc[b][mt][2], acc[b][mt][3]);
                #pragma unroll
                for (int qq = 0; qq < 3; qq++) {
                    float4 v = red[((qq * 2 + wrow) * 8 + b * 4 + mt) * 32 + lane];
                    r.x += v.x; r.y += v.y; r.z += v.z; r.w += v.w;
                }
                const int m0 = mt * 8 + c * 2;
                // d0:(g,2c) d1:(g,2c+1) d2:(g+8,2c) d3:(g+8,2c+1); rows=o, cols=m
                out[(size_t)m0       * ODIM + o0    ] = r.x;
                out[(size_t)(m0 + 1) * ODIM + o0    ] = r.y;
                out[(size_t)m0       * ODIM + o0 + 8] = r.z;
                out[(size_t)(m0 + 1) * ODIM + o0 + 8] = r.w;
            }
        }
    }
}

extern "C" void kernel_launch(void* const* d_in, const int* in_sizes, int n_in,
                              void* d_out, int out_size) {
    const float* x = (const float*)d_in[0];
    const float* w = (const float*)d_in[1];
    const float* s = (const float*)d_in[2];
    float* out = (float*)d_out;

    round_x_kernel<<<(MDIM * KDIM + 511) / 512, 512>>>(x);

    const size_t smem_bytes = SMEM_FLOATS * sizeof(float);
    cudaFuncSetAttribute(linear_tf32_mma,
                         cudaFuncAttributeMaxDynamicSharedMemorySize, (int)smem_bytes);
    linear_tf32_mma<<<ODIM / OTILE, NTHREADS, smem_bytes>>>(w, s, out);
}